// round 6
// baseline (speedup 1.0000x reference)
#include <cuda_runtime.h>
#include <math.h>

#define Nn   32
#define Cc   64
#define Tt   256
#define Vv   25
#define ICc  16
#define NSs  3
#define TV   6400
#define CTV  (Cc*TV)

typedef unsigned long long ull;

__device__ __forceinline__ ull pack2(float lo, float hi){
    ull r; asm("mov.b64 %0, {%1, %2};" : "=l"(r) : "f"(lo), "f"(hi)); return r;
}
__device__ __forceinline__ void fma2(ull &d, ull a, ull b){
    asm("fma.rn.f32x2 %0, %1, %2, %0;" : "+l"(d) : "l"(a), "l"(b));
}
__device__ __forceinline__ void unpk(float &lo, float &hi, ull v){
    asm("mov.b64 {%0, %1}, %2;" : "=f"(lo), "=f"(hi) : "l"(v));
}

// ---------------- scratch ----------
__device__ float g_a  [NSs*Nn*ICc*TV];
__device__ float g_b  [NSs*Nn*ICc*TV];
__device__ float g_att[NSs*Nn*Vv*Vv];
__device__ float g_gcn[Nn*Cc*TV];
__device__ float g_msg[Nn*Cc*TV];

// =====================================================================
// K1: fused conv_a + conv_b (unchanged — passed)
// =====================================================================
__global__ void __launch_bounds__(384, 2)
k_conv_ab(const float* __restrict__ h,
          const float* __restrict__ caw, const float* __restrict__ cab,
          const float* __restrict__ cbw, const float* __restrict__ cbb) {
    extern __shared__ __align__(16) float sm1[];
    float* sW = sm1;                 // [96][65]
    float* sH = sW + 96*65;          // [64][68]
    float* sB = sH + 64*68;          // [96]
    int n = blockIdx.y, p0 = blockIdx.x*64;
    int tid = threadIdx.x;
    for (int idx = tid; idx < 96*64; idx += 384) {
        int oc = idx>>6, c = idx&63;
        int i = oc/32, which = (oc%32)/16, o = oc%16;
        sW[oc*65 + c] = (which ? cbw : caw)[(i*ICc + o)*Cc + c];
    }
    if (tid < 96) {
        int oc = tid; int i = oc/32, which = (oc%32)/16, o = oc%16;
        sB[oc] = (which ? cbb : cab)[i*ICc + o];
    }
    for (int idx = tid; idx < 64*64; idx += 384) {
        int c = idx>>6, p = idx&63;
        sH[c*68 + p] = h[(size_t)n*CTV + (size_t)c*TV + p0 + p];
    }
    __syncthreads();
    int tx = tid & 15, ty = tid >> 4;
    int c0 = 4*tx, r0 = 4*ty;
    float acc[4][4];
#pragma unroll
    for (int a=0;a<4;a++)
#pragma unroll
        for (int b=0;b<4;b++) acc[a][b]=0.f;
#pragma unroll 4
    for (int k=0;k<64;k++){
        float4 bv = *(const float4*)&sH[k*68 + c0];
        float wv[4];
#pragma unroll
        for (int a=0;a<4;a++) wv[a] = sW[(r0+a)*65 + k];
#pragma unroll
        for (int a=0;a<4;a++){
            acc[a][0] += wv[a]*bv.x; acc[a][1] += wv[a]*bv.y;
            acc[a][2] += wv[a]*bv.z; acc[a][3] += wv[a]*bv.w;
        }
    }
    int i = r0/32, which = (r0%32)/16;
    float* out = which ? g_b : g_a;
#pragma unroll
    for (int a=0;a<4;a++){
        int oc = r0+a;
        int o = oc%16;
        float bias = sB[oc];
        size_t base = ((size_t)(i*Nn+n)*ICc + o)*TV + p0 + c0;
        float4 r = make_float4(acc[a][0]+bias, acc[a][1]+bias,
                               acc[a][2]+bias, acc[a][3]+bias);
        *(float4*)&out[base] = r;
    }
}

// =====================================================================
// K2: attention (unchanged)
// =====================================================================
__global__ void k_attn(const float* __restrict__ A, const float* __restrict__ PA) {
    int blk = blockIdx.x;
    int i = blk / Nn;
    __shared__ float sa[1600], sb[1600], lg[625];
    const float* ap = g_a + (size_t)blk*ICc*TV;
    const float* bp = g_b + (size_t)blk*ICc*TV;
    int tid = threadIdx.x;
    int v = tid/25, w = tid%25;
    float acc = 0.f;
    for (int kc = 0; kc < ICc*Tt; kc += 64) {
        __syncthreads();
        for (int idx = tid; idx < 1600; idx += 1024) {
            sa[idx] = ap[kc*25 + idx];
            sb[idx] = bp[kc*25 + idx];
        }
        __syncthreads();
        if (tid < 625) {
#pragma unroll
            for (int k=0;k<64;k++) acc += sa[k*25+v]*sb[k*25+w];
        }
    }
    if (tid < 625) lg[tid] = acc * (1.0f/4096.0f);
    __syncthreads();
    if (tid < 25) {
        float m = -1e30f;
#pragma unroll
        for (int vv=0; vv<25; vv++) m = fmaxf(m, lg[vv*25+tid]);
        float e[25]; float s = 0.f;
#pragma unroll
        for (int vv=0; vv<25; vv++){ e[vv]=expf(lg[vv*25+tid]-m); s+=e[vv]; }
        float inv = 1.0f/s;
#pragma unroll
        for (int vv=0; vv<25; vv++){
            g_att[(size_t)blk*625 + vv*25 + tid] =
                e[vv]*inv + A[i*625 + vv*25 + tid] + PA[i*625 + vv*25 + tid];
        }
    }
}

// =====================================================================
// K3: FUSED z + conv_d + BN + ReLU + residual; GEMM phase now FFMA2
// =====================================================================
__global__ void __launch_bounds__(256, 2)
k_gcn(const float* __restrict__ h,
      const float* __restrict__ cdw, const float* __restrict__ cdb,
      const float* __restrict__ gg, const float* __restrict__ gb,
      const float* __restrict__ gm, const float* __restrict__ gv) {
    extern __shared__ __align__(16) char smraw3[];
    float* sH  = (float*)smraw3;        // [64][112]
    float* sZ  = sH + 64*112;           // [64][68]
    ull*   sWd = (ull*)(sZ + 64*68);    // [64][66]
    float* sAtt= (float*)(sWd + 64*66); // [625]

    int n = blockIdx.y, p0 = blockIdx.x*64;
    int tb = p0/25;
    int tid = threadIdx.x;

    for (int idx = tid; idx < 64*112; idx += 256){
        int cp = idx/112, q = idx%112, tq = q/28, v = q%28;
        int t = tb + tq;
        sH[idx] = (v < 25 && t < Tt) ? h[(size_t)n*CTV + (size_t)cp*TV + t*25 + v] : 0.f;
    }

    int tx = tid & 15, ty = tid >> 4;
    int c0 = 4*tx, r0 = 4*ty;
    int pos = tid & 63, cpb = (tid>>6)*16;
    int p = p0 + pos;
    int wv_ = p % 25, tq0 = p/25 - tb;

    ull acc[4][2];
#pragma unroll
    for (int a=0;a<4;a++){ acc[a][0]=0ull; acc[a][1]=0ull; }

    for (int i=0;i<NSs;i++){
        __syncthreads();
        for (int idx = tid; idx < 625; idx += 256)
            sAtt[idx] = g_att[(size_t)(i*Nn+n)*625 + idx];
        for (int idx = tid; idx < 4096; idx += 256){
            int r = idx>>6, k = idx&63;
            float w = cdw[(size_t)i*4096 + r*64 + k];
            sWd[r*66 + k] = pack2(w, w);
        }
        __syncthreads();
        // ---- z phase
        {
            float av[28];
#pragma unroll
            for (int v=0;v<25;v++) av[v] = sAtt[v*25 + wv_];
            av[25]=0.f; av[26]=0.f; av[27]=0.f;
            int hbase = tq0*28;
#pragma unroll 4
            for (int j=0;j<16;j++){
                int cp = cpb + j;
                const float4* hp = (const float4*)&sH[cp*112 + hbase];
                float a2 = 0.f;
#pragma unroll
                for (int v4=0; v4<7; v4++){
                    float4 hv = hp[v4];
                    a2 += hv.x*av[4*v4] + hv.y*av[4*v4+1]
                        + hv.z*av[4*v4+2] + hv.w*av[4*v4+3];
                }
                sZ[cp*68 + pos] = a2;
            }
        }
        __syncthreads();
        // ---- FFMA2 GEMM accumulate
#pragma unroll 4
        for (int k=0;k<64;k+=2){
            ulonglong2 b0 = *(const ulonglong2*)&sZ[k*68 + c0];
            ulonglong2 b1 = *(const ulonglong2*)&sZ[(k+1)*68 + c0];
#pragma unroll
            for (int a=0;a<4;a++){
                ulonglong2 w2 = *(const ulonglong2*)&sWd[(r0+a)*66 + k];
                fma2(acc[a][0], w2.x, b0.x);
                fma2(acc[a][1], w2.x, b0.y);
                fma2(acc[a][0], w2.y, b1.x);
                fma2(acc[a][1], w2.y, b1.y);
            }
        }
    }
#pragma unroll
    for (int a=0;a<4;a++){
        int c = r0 + a;
        float bias = cdb[c] + cdb[64+c] + cdb[128+c];
        float scale = gg[c]*rsqrtf(gv[c]+1e-5f);
        float shift = gb[c] - gm[c]*scale + bias*scale;
        size_t ob = (size_t)n*CTV + (size_t)c*TV + p0 + c0;
        float4 hid = *(const float4*)&h[ob];
        float v0,v1,v2,v3;
        unpk(v0,v1,acc[a][0]); unpk(v2,v3,acc[a][1]);
        float4 o;
        o.x = fmaxf(v0*scale + shift + hid.x, 0.f);
        o.y = fmaxf(v1*scale + shift + hid.y, 0.f);
        o.z = fmaxf(v2*scale + shift + hid.z, 0.f);
        o.w = fmaxf(v3*scale + shift + hid.w, 0.f);
        *(float4*)&g_gcn[ob] = o;
    }
}

// =====================================================================
// K4: tcn — 64x128 block tile, 4 rows x 8 cols FFMA2 (1 B/MAC)
// =====================================================================
__global__ void __launch_bounds__(256, 2)
k_tcn(const float* __restrict__ hidden,
      const float* __restrict__ tw, const float* __restrict__ tb,
      const float* __restrict__ tg, const float* __restrict__ tbb,
      const float* __restrict__ tm, const float* __restrict__ tvv) {
    extern __shared__ __align__(16) char smraw4[];
    ull*   sWd = (ull*)smraw4;              // [64][74]
    float* sB  = (float*)(sWd + 64*74);     // [72][132]
    int n = blockIdx.y, p0 = blockIdx.x*128;
    int tid = threadIdx.x;
    int tx = tid & 15, ty = tid >> 4;
    int c0 = 8*tx, r0 = 4*ty;
    ull acc[4][4];
#pragma unroll
    for (int a=0;a<4;a++)
#pragma unroll
        for (int b=0;b<4;b++) acc[a][b]=0ull;

    for (int ch=0; ch<8; ch++){
        int ci8 = ch*8;
        __syncthreads();
        for (int idx = tid; idx < 64*72; idx += 256){
            int o = idx/72, r = idx%72;
            int ci = r/9, kk = r%9;
            float w = tw[((size_t)o*Cc + ci8 + ci)*9 + kk];
            sWd[o*74 + r] = pack2(w, w);
        }
        for (int idx = tid; idx < 72*128; idx += 256){
            int r = idx>>7, q = idx&127;
            int ci = r/9, kk = r%9;
            int fp = p0 + q + 25*kk - 100;
            sB[r*132 + q] = (fp >= 0 && fp < TV)
                ? g_gcn[(size_t)n*CTV + (size_t)(ci8+ci)*TV + fp] : 0.f;
        }
        __syncthreads();
#pragma unroll 2
        for (int k=0;k<72;k+=2){
            ulonglong2 bA = *(const ulonglong2*)&sB[k*132 + c0];
            ulonglong2 bB = *(const ulonglong2*)&sB[k*132 + c0 + 4];
            ulonglong2 cA = *(const ulonglong2*)&sB[(k+1)*132 + c0];
            ulonglong2 cB = *(const ulonglong2*)&sB[(k+1)*132 + c0 + 4];
#pragma unroll
            for (int a=0;a<4;a++){
                ulonglong2 w2 = *(const ulonglong2*)&sWd[(r0+a)*74 + k];
                fma2(acc[a][0], w2.x, bA.x);
                fma2(acc[a][1], w2.x, bA.y);
                fma2(acc[a][2], w2.x, bB.x);
                fma2(acc[a][3], w2.x, bB.y);
                fma2(acc[a][0], w2.y, cA.x);
                fma2(acc[a][1], w2.y, cA.y);
                fma2(acc[a][2], w2.y, cB.x);
                fma2(acc[a][3], w2.y, cB.y);
            }
        }
    }
#pragma unroll
    for (int a=0;a<4;a++){
        int o = r0 + a;
        float scale = tg[o]*rsqrtf(tvv[o]+1e-5f);
        float shift = tbb[o] - tm[o]*scale + tb[o]*scale;
        size_t ob = (size_t)n*CTV + (size_t)o*TV + p0 + c0;
        float4 h0 = *(const float4*)&hidden[ob];
        float4 h1 = *(const float4*)&hidden[ob+4];
        float v0,v1,v2,v3,v4,v5,v6,v7;
        unpk(v0,v1,acc[a][0]); unpk(v2,v3,acc[a][1]);
        unpk(v4,v5,acc[a][2]); unpk(v6,v7,acc[a][3]);
        float4 r0v, r1v;
        r0v.x = fmaxf(v0*scale + shift + h0.x, 0.f);
        r0v.y = fmaxf(v1*scale + shift + h0.y, 0.f);
        r0v.z = fmaxf(v2*scale + shift + h0.z, 0.f);
        r0v.w = fmaxf(v3*scale + shift + h0.w, 0.f);
        r1v.x = fmaxf(v4*scale + shift + h1.x, 0.f);
        r1v.y = fmaxf(v5*scale + shift + h1.y, 0.f);
        r1v.z = fmaxf(v6*scale + shift + h1.z, 0.f);
        r1v.w = fmaxf(v7*scale + shift + h1.w, 0.f);
        *(float4*)&g_msg[ob]   = r0v;
        *(float4*)&g_msg[ob+4] = r1v;
    }
}

// =====================================================================
// K5: GRU — 6 FFMA2 GEMMs + gates
// =====================================================================
__global__ void __launch_bounds__(256, 2)
k_gru(const float* __restrict__ feat,
      const float* __restrict__ hidden,
      const float* __restrict__ Wir, const float* __restrict__ Wii,
      const float* __restrict__ Win, const float* __restrict__ Whr,
      const float* __restrict__ Whi, const float* __restrict__ Whh,
      const float* __restrict__ bir, const float* __restrict__ bii,
      const float* __restrict__ bin, float* __restrict__ out) {
    extern __shared__ __align__(16) char smraw6[];
    float* sF  = (float*)smraw6;            // [64][68]
    float* sM  = sF + 64*68;                // [64][68]
    ull*   sWd = (ull*)(sM + 64*68);        // [64][66]
    int n = blockIdx.y, p0 = blockIdx.x*64;
    int tid = threadIdx.x;
    for (int idx = tid; idx < 4096; idx += 256) {
        int c = idx>>6, p = idx&63;
        sF[c*68+p] = feat [(size_t)n*CTV + (size_t)c*TV + p0 + p];
        sM[c*68+p] = g_msg[(size_t)n*CTV + (size_t)c*TV + p0 + p];
    }
    int tx = tid & 15, ty = tid >> 4;
    int c0 = 4*tx, r0 = 4*ty;

    auto pass = [&](const float* __restrict__ Wg, const float* __restrict__ Xs,
                    ull acc[4][2]){
        __syncthreads();
        for (int idx = tid; idx < 4096; idx += 256){
            float w = Wg[idx];
            sWd[(idx>>6)*66 + (idx&63)] = pack2(w, w);
        }
        __syncthreads();
#pragma unroll
        for (int a=0;a<4;a++){ acc[a][0]=0ull; acc[a][1]=0ull; }
#pragma unroll 4
        for (int k=0;k<64;k+=2){
            ulonglong2 b0 = *(const ulonglong2*)&Xs[k*68 + c0];
            ulonglong2 b1 = *(const ulonglong2*)&Xs[(k+1)*68 + c0];
#pragma unroll
            for (int a=0;a<4;a++){
                ulonglong2 w2 = *(const ulonglong2*)&sWd[(r0+a)*66 + k];
                fma2(acc[a][0], w2.x, b0.x);
                fma2(acc[a][1], w2.x, b0.y);
                fma2(acc[a][0], w2.y, b1.x);
                fma2(acc[a][1], w2.y, b1.y);
            }
        }
    };

    ull accA[4][2], accB[4][2];
    float rr[4][4], zz[4][4];

    pass(Wir, sF, accA);
    pass(Whr, sM, accB);
#pragma unroll
    for (int a=0;a<4;a++){
        float bv = bir[r0+a];
        float a0,a1,a2,a3,b0,b1,b2,b3;
        unpk(a0,a1,accA[a][0]); unpk(a2,a3,accA[a][1]);
        unpk(b0,b1,accB[a][0]); unpk(b2,b3,accB[a][1]);
        rr[a][0] = 1.0f/(1.0f + __expf(-(a0+bv+b0)));
        rr[a][1] = 1.0f/(1.0f + __expf(-(a1+bv+b1)));
        rr[a][2] = 1.0f/(1.0f + __expf(-(a2+bv+b2)));
        rr[a][3] = 1.0f/(1.0f + __expf(-(a3+bv+b3)));
    }
    pass(Wii, sF, accA);
    pass(Whi, sM, accB);
#pragma unroll
    for (int a=0;a<4;a++){
        float bv = bii[r0+a];
        float a0,a1,a2,a3,b0,b1,b2,b3;
        unpk(a0,a1,accA[a][0]); unpk(a2,a3,accA[a][1]);
        unpk(b0,b1,accB[a][0]); unpk(b2,b3,accB[a][1]);
        zz[a][0] = 1.0f/(1.0f + __expf(-(a0+bv+b0)));
        zz[a][1] = 1.0f/(1.0f + __expf(-(a1+bv+b1)));
        zz[a][2] = 1.0f/(1.0f + __expf(-(a2+bv+b2)));
        zz[a][3] = 1.0f/(1.0f + __expf(-(a3+bv+b3)));
    }
    pass(Win, sF, accA);
    pass(Whh, sM, accB);
#pragma unroll
    for (int a=0;a<4;a++){
        int c = r0+a;
        float bv = bin[c];
        float a0,a1,a2,a3,b0,b1,b2,b3;
        unpk(a0,a1,accA[a][0]); unpk(a2,a3,accA[a][1]);
        unpk(b0,b1,accB[a][0]); unpk(b2,b3,accB[a][1]);
        float xs[4] = {a0+bv+rr[a][0]*b0, a1+bv+rr[a][1]*b1,
                       a2+bv+rr[a][2]*b2, a3+bv+rr[a][3]*b3};
        size_t ob = (size_t)n*CTV + (size_t)c*TV + p0 + c0;
        float4 hid = *(const float4*)&hidden[ob];
        float hv[4] = {hid.x, hid.y, hid.z, hid.w};
        float4 o;
        float* op = &o.x;
#pragma unroll
        for (int b=0;b<4;b++){
            float e = __expf(-2.0f*xs[b]);
            float nn = (1.0f - e)/(1.0f + e);
            op[b] = (1.0f - zz[a][b])*nn + zz[a][b]*hv[b];
        }
        *(float4*)&out[ob] = o;
    }
}

// =====================================================================
extern "C" void kernel_launch(void* const* d_in, const int* in_sizes, int n_in,
                              void* d_out, int out_size) {
    const float* feature = (const float*)d_in[0];
    const float* hidden  = (const float*)d_in[1];
    const float* A   = (const float*)d_in[2];
    const float* PA  = (const float*)d_in[3];
    const float* caw = (const float*)d_in[4];
    const float* cab = (const float*)d_in[5];
    const float* cbw = (const float*)d_in[6];
    const float* cbb = (const float*)d_in[7];
    const float* cdw = (const float*)d_in[8];
    const float* cdb = (const float*)d_in[9];
    const float* gg  = (const float*)d_in[10];
    const float* gb  = (const float*)d_in[11];
    const float* gm  = (const float*)d_in[12];
    const float* gv  = (const float*)d_in[13];
    const float* tw  = (const float*)d_in[14];
    const float* tb  = (const float*)d_in[15];
    const float* tg  = (const float*)d_in[16];
    const float* tbb = (const float*)d_in[17];
    const float* tm  = (const float*)d_in[18];
    const float* tvv = (const float*)d_in[19];

    const float *Wir,*Wii,*Win,*Whr,*Whi,*Whh,*bir,*bii,*bin;
    if (in_sizes[21] == 64) {
        Wir=(const float*)d_in[20]; bir=(const float*)d_in[21];
        Wii=(const float*)d_in[22]; bii=(const float*)d_in[23];
        Win=(const float*)d_in[24]; bin=(const float*)d_in[25];
        Whr=(const float*)d_in[26]; Whi=(const float*)d_in[27]; Whh=(const float*)d_in[28];
    } else {
        Wir=(const float*)d_in[20]; Wii=(const float*)d_in[21]; Win=(const float*)d_in[22];
        Whr=(const float*)d_in[23]; Whi=(const float*)d_in[24]; Whh=(const float*)d_in[25];
        bir=(const float*)d_in[26]; bii=(const float*)d_in[27]; bin=(const float*)d_in[28];
    }

    const int SM1 = (96*65 + 64*68 + 96) * 4;                      // 42368
    const int SM3 = (64*112 + 64*68)*4 + 64*66*8 + 625*4;          // 82372
    const int SM4 = 64*74*8 + 72*132*4;                            // 75904
    const int SM5 = 2*64*68*4 + 64*66*8;                           // 68608
    cudaFuncSetAttribute(k_conv_ab, cudaFuncAttributeMaxDynamicSharedMemorySize, SM1);
    cudaFuncSetAttribute(k_gcn,  cudaFuncAttributeMaxDynamicSharedMemorySize, SM3);
    cudaFuncSetAttribute(k_tcn,  cudaFuncAttributeMaxDynamicSharedMemorySize, SM4);
    cudaFuncSetAttribute(k_gru,  cudaFuncAttributeMaxDynamicSharedMemorySize, SM5);

    k_conv_ab<<<dim3(100, Nn), 384, SM1>>>(hidden, caw, cab, cbw, cbb);
    k_attn   <<<NSs*Nn, 1024>>>(A, PA);
    k_gcn    <<<dim3(100, Nn), 256, SM3>>>(hidden, cdw, cdb, gg, gb, gm, gv);
    k_tcn    <<<dim3(50,  Nn), 256, SM4>>>(hidden, tw, tb, tg, tbb, tm, tvv);
    k_gru    <<<dim3(100, Nn), 256, SM5>>>(feature, hidden,
                                           Wir, Wii, Win, Whr, Whi, Whh,
                                           bir, bii, bin, (float*)d_out);
}

// round 7
// speedup vs baseline: 1.1468x; 1.1468x over previous
#include <cuda_runtime.h>
#include <math.h>

#define Nn   32
#define Cc   64
#define Tt   256
#define Vv   25
#define ICc  16
#define NSs  3
#define TV   6400
#define CTV  (Cc*TV)

typedef unsigned long long ull;

__device__ __forceinline__ ull pack2(float lo, float hi){
    ull r; asm("mov.b64 %0, {%1, %2};" : "=l"(r) : "f"(lo), "f"(hi)); return r;
}
__device__ __forceinline__ void fma2(ull &d, ull a, ull b){
    asm("fma.rn.f32x2 %0, %1, %2, %0;" : "+l"(d) : "l"(a), "l"(b));
}
__device__ __forceinline__ void unpk(float &lo, float &hi, ull v){
    asm("mov.b64 {%0, %1}, %2;" : "=f"(lo), "=f"(hi) : "l"(v));
}

// ---------------- scratch ----------
__device__ float g_a  [NSs*Nn*ICc*TV];
__device__ float g_b  [NSs*Nn*ICc*TV];
__device__ float g_att[NSs*Nn*Vv*Vv];
__device__ float g_gcn[Nn*Cc*TV];
__device__ float g_msg[Nn*Cc*TV];

// =====================================================================
// K1: fused conv_a + conv_b (unchanged — proven)
// =====================================================================
__global__ void __launch_bounds__(384, 2)
k_conv_ab(const float* __restrict__ h,
          const float* __restrict__ caw, const float* __restrict__ cab,
          const float* __restrict__ cbw, const float* __restrict__ cbb) {
    extern __shared__ __align__(16) float sm1[];
    float* sW = sm1;                 // [96][65]
    float* sH = sW + 96*65;          // [64][68]
    float* sB = sH + 64*68;          // [96]
    int n = blockIdx.y, p0 = blockIdx.x*64;
    int tid = threadIdx.x;
    for (int idx = tid; idx < 96*64; idx += 384) {
        int oc = idx>>6, c = idx&63;
        int i = oc/32, which = (oc%32)/16, o = oc%16;
        sW[oc*65 + c] = (which ? cbw : caw)[(i*ICc + o)*Cc + c];
    }
    if (tid < 96) {
        int oc = tid; int i = oc/32, which = (oc%32)/16, o = oc%16;
        sB[oc] = (which ? cbb : cab)[i*ICc + o];
    }
    for (int idx = tid; idx < 64*64; idx += 384) {
        int c = idx>>6, p = idx&63;
        sH[c*68 + p] = h[(size_t)n*CTV + (size_t)c*TV + p0 + p];
    }
    __syncthreads();
    int tx = tid & 15, ty = tid >> 4;
    int c0 = 4*tx, r0 = 4*ty;
    float acc[4][4];
#pragma unroll
    for (int a=0;a<4;a++)
#pragma unroll
        for (int b=0;b<4;b++) acc[a][b]=0.f;
#pragma unroll 4
    for (int k=0;k<64;k++){
        float4 bv = *(const float4*)&sH[k*68 + c0];
        float wv[4];
#pragma unroll
        for (int a=0;a<4;a++) wv[a] = sW[(r0+a)*65 + k];
#pragma unroll
        for (int a=0;a<4;a++){
            acc[a][0] += wv[a]*bv.x; acc[a][1] += wv[a]*bv.y;
            acc[a][2] += wv[a]*bv.z; acc[a][3] += wv[a]*bv.w;
        }
    }
    int i = r0/32, which = (r0%32)/16;
    float* out = which ? g_b : g_a;
#pragma unroll
    for (int a=0;a<4;a++){
        int oc = r0+a;
        int o = oc%16;
        float bias = sB[oc];
        size_t base = ((size_t)(i*Nn+n)*ICc + o)*TV + p0 + c0;
        float4 r = make_float4(acc[a][0]+bias, acc[a][1]+bias,
                               acc[a][2]+bias, acc[a][3]+bias);
        *(float4*)&out[base] = r;
    }
}

// =====================================================================
// K2: attention (unchanged)
// =====================================================================
__global__ void k_attn(const float* __restrict__ A, const float* __restrict__ PA) {
    int blk = blockIdx.x;
    int i = blk / Nn;
    __shared__ float sa[1600], sb[1600], lg[625];
    const float* ap = g_a + (size_t)blk*ICc*TV;
    const float* bp = g_b + (size_t)blk*ICc*TV;
    int tid = threadIdx.x;
    int v = tid/25, w = tid%25;
    float acc = 0.f;
    for (int kc = 0; kc < ICc*Tt; kc += 64) {
        __syncthreads();
        for (int idx = tid; idx < 1600; idx += 1024) {
            sa[idx] = ap[kc*25 + idx];
            sb[idx] = bp[kc*25 + idx];
        }
        __syncthreads();
        if (tid < 625) {
#pragma unroll
            for (int k=0;k<64;k++) acc += sa[k*25+v]*sb[k*25+w];
        }
    }
    if (tid < 625) lg[tid] = acc * (1.0f/4096.0f);
    __syncthreads();
    if (tid < 25) {
        float m = -1e30f;
#pragma unroll
        for (int vv=0; vv<25; vv++) m = fmaxf(m, lg[vv*25+tid]);
        float e[25]; float s = 0.f;
#pragma unroll
        for (int vv=0; vv<25; vv++){ e[vv]=expf(lg[vv*25+tid]-m); s+=e[vv]; }
        float inv = 1.0f/s;
#pragma unroll
        for (int vv=0; vv<25; vv++){
            g_att[(size_t)blk*625 + vv*25 + tid] =
                e[vv]*inv + A[i*625 + vv*25 + tid] + PA[i*625 + vv*25 + tid];
        }
    }
}

// =====================================================================
// K3: FUSED z + conv_d + BN + ReLU + residual (scalar occ-3 — best measured)
// =====================================================================
__global__ void __launch_bounds__(256, 3)
k_gcn(const float* __restrict__ h,
      const float* __restrict__ cdw, const float* __restrict__ cdb,
      const float* __restrict__ gg, const float* __restrict__ gb,
      const float* __restrict__ gm, const float* __restrict__ gv) {
    extern __shared__ __align__(16) float sm3[];
    float* sH  = sm3;                // [64][112]
    float* sZ  = sH + 64*112;        // [64][68]
    float* sW  = sZ + 64*68;         // [64][65]
    float* sAtt= sW + 64*65;         // [625]

    int n = blockIdx.y, p0 = blockIdx.x*64;
    int tb = p0/25;
    int tid = threadIdx.x;

    for (int idx = tid; idx < 64*112; idx += 256){
        int cp = idx/112, q = idx%112, tq = q/28, v = q%28;
        int t = tb + tq;
        sH[idx] = (v < 25 && t < Tt) ? h[(size_t)n*CTV + (size_t)cp*TV + t*25 + v] : 0.f;
    }

    int tx = tid & 15, ty = tid >> 4;
    int c0 = 4*tx, r0 = 4*ty;
    int pos = tid & 63, cpb = (tid>>6)*16;
    int p = p0 + pos;
    int wv_ = p % 25, tq0 = p/25 - tb;

    float acc[4][4];
#pragma unroll
    for (int a=0;a<4;a++)
#pragma unroll
        for (int b=0;b<4;b++) acc[a][b]=0.f;

    for (int i=0;i<NSs;i++){
        __syncthreads();
        for (int idx = tid; idx < 625; idx += 256)
            sAtt[idx] = g_att[(size_t)(i*Nn+n)*625 + idx];
        for (int idx = tid; idx < 4096; idx += 256){
            int r = idx>>6, k = idx&63;
            sW[r*65 + k] = cdw[(size_t)i*4096 + r*64 + k];
        }
        __syncthreads();
        {
            float av[28];
#pragma unroll
            for (int v=0;v<25;v++) av[v] = sAtt[v*25 + wv_];
            av[25]=0.f; av[26]=0.f; av[27]=0.f;
            int hbase = tq0*28;
#pragma unroll 4
            for (int j=0;j<16;j++){
                int cp = cpb + j;
                const float4* hp = (const float4*)&sH[cp*112 + hbase];
                float a2 = 0.f;
#pragma unroll
                for (int v4=0; v4<7; v4++){
                    float4 hv = hp[v4];
                    a2 += hv.x*av[4*v4] + hv.y*av[4*v4+1]
                        + hv.z*av[4*v4+2] + hv.w*av[4*v4+3];
                }
                sZ[cp*68 + pos] = a2;
            }
        }
        __syncthreads();
#pragma unroll 4
        for (int k=0;k<64;k++){
            float4 bv = *(const float4*)&sZ[k*68 + c0];
            float wv[4];
#pragma unroll
            for (int a=0;a<4;a++) wv[a] = sW[(r0+a)*65 + k];
#pragma unroll
            for (int a=0;a<4;a++){
                acc[a][0] += wv[a]*bv.x; acc[a][1] += wv[a]*bv.y;
                acc[a][2] += wv[a]*bv.z; acc[a][3] += wv[a]*bv.w;
            }
        }
    }
#pragma unroll
    for (int a=0;a<4;a++){
        int c = r0 + a;
        float bias = cdb[c] + cdb[64+c] + cdb[128+c];
        float scale = gg[c]*rsqrtf(gv[c]+1e-5f);
        float shift = gb[c] - gm[c]*scale + bias*scale;
        size_t ob = (size_t)n*CTV + (size_t)c*TV + p0 + c0;
        float4 hid = *(const float4*)&h[ob];
        float4 o;
        o.x = fmaxf(acc[a][0]*scale + shift + hid.x, 0.f);
        o.y = fmaxf(acc[a][1]*scale + shift + hid.y, 0.f);
        o.z = fmaxf(acc[a][2]*scale + shift + hid.z, 0.f);
        o.w = fmaxf(acc[a][3]*scale + shift + hid.w, 0.f);
        *(float4*)&g_gcn[ob] = o;
    }
}

// =====================================================================
// K4: tcn — TALL 8x4 FFMA2 tile, block 64x128, weight-broadcast layout
// =====================================================================
__global__ void __launch_bounds__(256, 2)
k_tcn(const float* __restrict__ hidden,
      const float* __restrict__ tw, const float* __restrict__ tb,
      const float* __restrict__ tg, const float* __restrict__ tbb,
      const float* __restrict__ tm, const float* __restrict__ tvv) {
    extern __shared__ __align__(16) char smraw4[];
    ull*   sWd = (ull*)smraw4;              // [64][74]
    float* sB  = (float*)(sWd + 64*74);     // [72][132]
    int n = blockIdx.y, p0 = blockIdx.x*128;
    int tid = threadIdx.x;
    int tx = tid & 31, ty = tid >> 5;       // ty 0..7
    int c0 = 4*tx, r0 = 8*ty;
    ull acc[8][2];
#pragma unroll
    for (int a=0;a<8;a++){ acc[a][0]=0ull; acc[a][1]=0ull; }

    for (int ch=0; ch<8; ch++){
        int ci8 = ch*8;
        __syncthreads();
        for (int idx = tid; idx < 64*72; idx += 256){
            int o = idx/72, r = idx%72;
            int ci = r/9, kk = r%9;
            float w = tw[((size_t)o*Cc + ci8 + ci)*9 + kk];
            sWd[o*74 + r] = pack2(w, w);
        }
        for (int idx = tid; idx < 72*128; idx += 256){
            int r = idx>>7, q = idx&127;
            int ci = r/9, kk = r%9;
            int fp = p0 + q + 25*kk - 100;
            sB[r*132 + q] = (fp >= 0 && fp < TV)
                ? g_gcn[(size_t)n*CTV + (size_t)(ci8+ci)*TV + fp] : 0.f;
        }
        __syncthreads();
#pragma unroll 2
        for (int k=0;k<72;k+=2){
            ulonglong2 b0 = *(const ulonglong2*)&sB[k*132 + c0];
            ulonglong2 b1 = *(const ulonglong2*)&sB[(k+1)*132 + c0];
#pragma unroll
            for (int a=0;a<8;a++){
                // all 32 lanes read same address -> broadcast
                ulonglong2 w2 = *(const ulonglong2*)&sWd[(r0+a)*74 + k];
                fma2(acc[a][0], w2.x, b0.x);
                fma2(acc[a][1], w2.x, b0.y);
                fma2(acc[a][0], w2.y, b1.x);
                fma2(acc[a][1], w2.y, b1.y);
            }
        }
    }
#pragma unroll
    for (int a=0;a<8;a++){
        int o = r0 + a;
        float scale = tg[o]*rsqrtf(tvv[o]+1e-5f);
        float shift = tbb[o] - tm[o]*scale + tb[o]*scale;
        size_t ob = (size_t)n*CTV + (size_t)o*TV + p0 + c0;
        float4 hid = *(const float4*)&hidden[ob];
        float v0,v1,v2,v3;
        unpk(v0,v1,acc[a][0]); unpk(v2,v3,acc[a][1]);
        float4 r;
        r.x = fmaxf(v0*scale + shift + hid.x, 0.f);
        r.y = fmaxf(v1*scale + shift + hid.y, 0.f);
        r.z = fmaxf(v2*scale + shift + hid.z, 0.f);
        r.w = fmaxf(v3*scale + shift + hid.w, 0.f);
        *(float4*)&g_msg[ob] = r;
    }
}

// =====================================================================
// K5: GRU — scalar occ-3 (best measured)
// =====================================================================
__global__ void __launch_bounds__(256, 3)
k_gru(const float* __restrict__ feat,
      const float* __restrict__ hidden,
      const float* __restrict__ Wir, const float* __restrict__ Wii,
      const float* __restrict__ Win, const float* __restrict__ Whr,
      const float* __restrict__ Whi, const float* __restrict__ Whh,
      const float* __restrict__ bir, const float* __restrict__ bii,
      const float* __restrict__ bin, float* __restrict__ out) {
    extern __shared__ __align__(16) float sm6[];
    float* sF = sm6;                 // [64][68]
    float* sM = sF + 64*68;          // [64][68]
    float* sW = sM + 64*68;          // [64][65]
    int n = blockIdx.y, p0 = blockIdx.x*64;
    int tid = threadIdx.x;
    for (int idx = tid; idx < 4096; idx += 256) {
        int c = idx>>6, p = idx&63;
        sF[c*68+p] = feat [(size_t)n*CTV + (size_t)c*TV + p0 + p];
        sM[c*68+p] = g_msg[(size_t)n*CTV + (size_t)c*TV + p0 + p];
    }
    int tx = tid & 15, ty = tid >> 4;
    int c0 = 4*tx, r0 = 4*ty;

    auto pass = [&](const float* __restrict__ Wg, const float* __restrict__ Xs,
                    float acc[4][4]){
        __syncthreads();
        for (int idx = tid; idx < 4096; idx += 256)
            sW[(idx>>6)*65 + (idx&63)] = Wg[idx];
        __syncthreads();
#pragma unroll
        for (int a=0;a<4;a++)
#pragma unroll
            for (int b=0;b<4;b++) acc[a][b]=0.f;
#pragma unroll 4
        for (int k=0;k<64;k++){
            float4 bv = *(const float4*)&Xs[k*68 + c0];
            float wv[4];
#pragma unroll
            for (int a=0;a<4;a++) wv[a] = sW[(r0+a)*65 + k];
#pragma unroll
            for (int a=0;a<4;a++){
                acc[a][0] += wv[a]*bv.x; acc[a][1] += wv[a]*bv.y;
                acc[a][2] += wv[a]*bv.z; acc[a][3] += wv[a]*bv.w;
            }
        }
    };

    float accA[4][4], accB[4][4];
    float rr[4][4], zz[4][4];

    pass(Wir, sF, accA);
    pass(Whr, sM, accB);
#pragma unroll
    for (int a=0;a<4;a++){
        float bv = bir[r0+a];
#pragma unroll
        for (int b=0;b<4;b++)
            rr[a][b] = 1.0f/(1.0f + __expf(-(accA[a][b]+bv+accB[a][b])));
    }
    pass(Wii, sF, accA);
    pass(Whi, sM, accB);
#pragma unroll
    for (int a=0;a<4;a++){
        float bv = bii[r0+a];
#pragma unroll
        for (int b=0;b<4;b++)
            zz[a][b] = 1.0f/(1.0f + __expf(-(accA[a][b]+bv+accB[a][b])));
    }
    pass(Win, sF, accA);
    pass(Whh, sM, accB);
#pragma unroll
    for (int a=0;a<4;a++){
        int c = r0+a;
        float bv = bin[c];
        size_t ob = (size_t)n*CTV + (size_t)c*TV + p0 + c0;
        float4 hid = *(const float4*)&hidden[ob];
        float hv[4] = {hid.x, hid.y, hid.z, hid.w};
        float4 o;
        float* op = &o.x;
#pragma unroll
        for (int b=0;b<4;b++){
            float x = accA[a][b] + bv + rr[a][b]*accB[a][b];
            float e = __expf(-2.0f*x);
            float nn = (1.0f - e)/(1.0f + e);
            op[b] = (1.0f - zz[a][b])*nn + zz[a][b]*hv[b];
        }
        *(float4*)&out[ob] = o;
    }
}

// =====================================================================
extern "C" void kernel_launch(void* const* d_in, const int* in_sizes, int n_in,
                              void* d_out, int out_size) {
    const float* feature = (const float*)d_in[0];
    const float* hidden  = (const float*)d_in[1];
    const float* A   = (const float*)d_in[2];
    const float* PA  = (const float*)d_in[3];
    const float* caw = (const float*)d_in[4];
    const float* cab = (const float*)d_in[5];
    const float* cbw = (const float*)d_in[6];
    const float* cbb = (const float*)d_in[7];
    const float* cdw = (const float*)d_in[8];
    const float* cdb = (const float*)d_in[9];
    const float* gg  = (const float*)d_in[10];
    const float* gb  = (const float*)d_in[11];
    const float* gm  = (const float*)d_in[12];
    const float* gv  = (const float*)d_in[13];
    const float* tw  = (const float*)d_in[14];
    const float* tb  = (const float*)d_in[15];
    const float* tg  = (const float*)d_in[16];
    const float* tbb = (const float*)d_in[17];
    const float* tm  = (const float*)d_in[18];
    const float* tvv = (const float*)d_in[19];

    const float *Wir,*Wii,*Win,*Whr,*Whi,*Whh,*bir,*bii,*bin;
    if (in_sizes[21] == 64) {
        Wir=(const float*)d_in[20]; bir=(const float*)d_in[21];
        Wii=(const float*)d_in[22]; bii=(const float*)d_in[23];
        Win=(const float*)d_in[24]; bin=(const float*)d_in[25];
        Whr=(const float*)d_in[26]; Whi=(const float*)d_in[27]; Whh=(const float*)d_in[28];
    } else {
        Wir=(const float*)d_in[20]; Wii=(const float*)d_in[21]; Win=(const float*)d_in[22];
        Whr=(const float*)d_in[23]; Whi=(const float*)d_in[24]; Whh=(const float*)d_in[25];
        bir=(const float*)d_in[26]; bii=(const float*)d_in[27]; bin=(const float*)d_in[28];
    }

    const int SM1 = (96*65 + 64*68 + 96) * 4;                // 42368
    const int SM3 = (64*112 + 64*68 + 64*65 + 625) * 4;      // 65220
    const int SM4 = 64*74*8 + 72*132*4;                      // 75904
    const int SM5 = (2*64*68 + 64*65) * 4;                   // 51456
    cudaFuncSetAttribute(k_conv_ab, cudaFuncAttributeMaxDynamicSharedMemorySize, SM1);
    cudaFuncSetAttribute(k_gcn,  cudaFuncAttributeMaxDynamicSharedMemorySize, SM3);
    cudaFuncSetAttribute(k_tcn,  cudaFuncAttributeMaxDynamicSharedMemorySize, SM4);
    cudaFuncSetAttribute(k_gru,  cudaFuncAttributeMaxDynamicSharedMemorySize, SM5);

    k_conv_ab<<<dim3(100, Nn), 384, SM1>>>(hidden, caw, cab, cbw, cbb);
    k_attn   <<<NSs*Nn, 1024>>>(A, PA);
    k_gcn    <<<dim3(100, Nn), 256, SM3>>>(hidden, cdw, cdb, gg, gb, gm, gv);
    k_tcn    <<<dim3(50,  Nn), 256, SM4>>>(hidden, tw, tb, tg, tbb, tm, tvv);
    k_gru    <<<dim3(100, Nn), 256, SM5>>>(feature, hidden,
                                           Wir, Wii, Win, Whr, Whi, Whh,
                                           bir, bii, bin, (float*)d_out);
}